// round 3
// baseline (speedup 1.0000x reference)
#include <cuda_runtime.h>

#define BB   8192
#define NW   4
#define LL   16
#define EE   128
#define HH   128
#define VV   64
#define BN_TOT (BB*NW)
#define G4H  512

typedef unsigned long long u64;

__device__ __align__(16) float g_G[VV * G4H];
__device__ __align__(16) float g_reps[(size_t)BN_TOT * HH];
__device__ int g_perm[BN_TOT];
__device__ int g_hist[16];
__device__ int g_cursor[16];

__device__ __forceinline__ u64 pk(float a, float b) {
    u64 v; asm("mov.b64 %0, {%1, %2};" : "=l"(v) : "f"(a), "f"(b)); return v;
}
__device__ __forceinline__ void unpk(u64 v, float& a, float& b) {
    asm("mov.b64 {%0, %1}, %2;" : "=f"(a), "=f"(b) : "l"(v));
}
__device__ __forceinline__ float sigm(float x) {
    return __fdividef(1.f, 1.f + __expf(-x));
}
__device__ __forceinline__ float tanh_f(float x) {
    return fmaf(-2.f, __fdividef(1.f, 1.f + __expf(2.f * x)), 1.f);
}

// ---- G[v][j] = emb[v] . W_ih[j] + b_ih[j] + b_hh[j] ----
__global__ void k_gates(const float* __restrict__ emb, const float* __restrict__ Wih,
                        const float* __restrict__ bih, const float* __restrict__ bhh) {
    int v = blockIdx.x, j = threadIdx.x;
    const float* e = emb + v * EE;
    const float* w = Wih + j * EE;
    float s = bih[j] + bhh[j];
#pragma unroll 8
    for (int k = 0; k < EE; ++k) s = fmaf(e[k], w[k], s);
    g_G[v * G4H + j] = s;
}

// ---- counting sort by length, descending (bin = 16 - len) ----
__global__ void k_zero() { if (threadIdx.x < 16) g_hist[threadIdx.x] = 0; }

__global__ void k_hist(const int* __restrict__ lengths) {
    __shared__ int sh[16];
    int tid = threadIdx.x;
    if (tid < 16) sh[tid] = 0;
    __syncthreads();
    int bn = blockIdx.x * 256 + tid;
    atomicAdd(&sh[16 - lengths[bn]], 1);
    __syncthreads();
    if (tid < 16) atomicAdd(&g_hist[tid], sh[tid]);
}

__global__ void k_scan() {
    int cum = 0;
    for (int b = 0; b < 16; ++b) { g_cursor[b] = cum; cum += g_hist[b]; }
}

__global__ void k_scatter(const int* __restrict__ lengths) {
    __shared__ int cnt[16], base[16];
    int tid = threadIdx.x;
    if (tid < 16) cnt[tid] = 0;
    __syncthreads();
    int bn  = blockIdx.x * 256 + tid;
    int bin = 16 - lengths[bn];
    int rank = atomicAdd(&cnt[bin], 1);
    __syncthreads();
    if (tid < 16) base[tid] = atomicAdd(&g_cursor[tid], cnt[tid]);
    __syncthreads();
    g_perm[base[bin] + rank] = bn;
}

// ---- masked LSTM over length-sorted rows ----
// CTA = 32 rows, 256 threads. warp = (rh,ch): rh owns 8 rows, ch a 64-wide
// hidden half. Thread cols {g*128 + 64*ch + 2*lane, +1}: all 4 gates of one
// hidden pair in one thread -> c stays in registers, update is thread-local.
__global__ __launch_bounds__(256, 2)
void k_lstm(const int* __restrict__ word_ids, const int* __restrict__ lengths,
            const float* __restrict__ Whh) {
    __shared__ __align__(16) float sH[32][128];
    __shared__ __align__(16) float sW[8][514];   // k-tile of W_hh, [k][j], padded
    __shared__ int sBn[32], sLen[32], sWid[32][LL];
    __shared__ int sMax;

    int tid  = threadIdx.x;
    int lane = tid & 31;
    int wrp  = tid >> 5;
    int rh   = wrp >> 1;
    int ch   = wrp & 1;
    int base = blockIdx.x * 32;
    int colh = 64 * ch + 2 * lane;

    for (int i = tid; i < 32; i += 256) {
        int bn = g_perm[base + i];
        sBn[i] = bn; sLen[i] = lengths[bn];
    }
    __syncthreads();
    for (int i = tid; i < 32 * LL; i += 256) {
        int r = i >> 4, t = i & 15;
        sWid[r][t] = word_ids[sBn[r] * LL + t];
    }
    for (int i = tid; i < 32 * 128; i += 256) (&sH[0][0])[i] = 0.f;
    if (tid == 0) {
        int m = 0;
        for (int r = 0; r < 32; ++r) m = max(m, sLen[r]);
        sMax = m;
    }
    __syncthreads();
    int maxLen = sMax;

    float c[8][2];
#pragma unroll
    for (int r = 0; r < 8; ++r) { c[r][0] = 0.f; c[r][1] = 0.f; }

    for (int t = 0; t < maxLen; ++t) {
        u64 acc[8][4];
#pragma unroll
        for (int r = 0; r < 8; ++r) {
            const u64* Gp = (const u64*)(g_G + sWid[rh * 8 + r][t] * G4H);
            int off = colh >> 1;
#pragma unroll
            for (int g = 0; g < 4; ++g) acc[r][g] = Gp[g * 64 + off];
        }
        for (int kk = 0; kk < 128; kk += 8) {
            __syncthreads();
#pragma unroll
            for (int u = tid; u < 2048; u += 256) {  // 2048 float2 covers 8k x 512j
                int j = u >> 2, k2 = u & 3;
                float2 w2 = *(const float2*)(Whh + j * 128 + kk + k2 * 2);
                sW[k2 * 2 + 0][j] = w2.x;
                sW[k2 * 2 + 1][j] = w2.y;
            }
            __syncthreads();
#pragma unroll
            for (int tt = 0; tt < 8; ++tt) {
                u64 hp[8];
#pragma unroll
                for (int r = 0; r < 8; ++r) {
                    float h = sH[rh * 8 + r][kk + tt];   // broadcast LDS
                    asm("mov.b64 %0, {%1, %1};" : "=l"(hp[r]) : "f"(h));
                }
#pragma unroll
                for (int g = 0; g < 4; ++g) {
                    u64 w = *(const u64*)(&sW[tt][g * 128 + colh]);
#pragma unroll
                    for (int r = 0; r < 8; ++r)
                        asm("fma.rn.f32x2 %0, %1, %2, %0;"
                            : "+l"(acc[r][g]) : "l"(hp[r]), "l"(w));
                }
            }
        }
        __syncthreads();   // all sH reads done before sH writes below
#pragma unroll
        for (int r = 0; r < 8; ++r) {
            int row = rh * 8 + r;
            if (t < sLen[row]) {
                float i0, i1, f0, f1, gg0, gg1, o0, o1;
                unpk(acc[r][0], i0, i1); unpk(acc[r][1], f0, f1);
                unpk(acc[r][2], gg0, gg1); unpk(acc[r][3], o0, o1);
                float c0 = fmaf(sigm(f0), c[r][0], sigm(i0) * tanh_f(gg0));
                float c1 = fmaf(sigm(f1), c[r][1], sigm(i1) * tanh_f(gg1));
                c[r][0] = c0; c[r][1] = c1;
                *(u64*)(&sH[row][colh]) = pk(sigm(o0) * tanh_f(c0),
                                             sigm(o1) * tanh_f(c1));
            }
        }
    }
#pragma unroll
    for (int r = 0; r < 8; ++r) {
        size_t bn = (size_t)sBn[rh * 8 + r];
        *(u64*)(g_reps + bn * HH + colh) = pk(c[r][0], c[r][1]);
    }
}

// ---- head: cos 4x4 -> conv1 relu -> conv2 relu -> scorer -> sigmoid ----
__global__ void k_head(const float* __restrict__ c1w, const float* __restrict__ c1b,
                       const float* __restrict__ c2w, const float* __restrict__ c2b,
                       const float* __restrict__ scw, const float* __restrict__ scb,
                       float* __restrict__ out) {
    int gw   = blockIdx.x * 8 + (threadIdx.x >> 5);   // one warp per batch b
    int lane = threadIdx.x & 31;
    if (gw >= BB) return;

    const float* rp = g_reps + (size_t)gw * (NW * HH);
    float4 rv[4];
#pragma unroll
    for (int i = 0; i < 4; ++i)
        rv[i] = *(const float4*)(rp + i * HH + lane * 4);

    const int pi[10] = {0,0,0,0,1,1,1,2,2,3};
    const int pj[10] = {0,1,2,3,1,2,3,2,3,3};
    float dots[10];
#pragma unroll
    for (int d = 0; d < 10; ++d) {
        float4 a = rv[pi[d]], b = rv[pj[d]];
        float s = a.x*b.x + a.y*b.y + a.z*b.z + a.w*b.w;
#pragma unroll
        for (int o = 16; o; o >>= 1) s += __shfl_xor_sync(0xffffffffu, s, o);
        dots[d] = s;
    }
    if (lane) return;

    float nn[4] = { rsqrtf(dots[0]), rsqrtf(dots[4]), rsqrtf(dots[7]), rsqrtf(dots[9]) };
    const int dmap[4][4] = {{0,1,2,3},{1,4,5,6},{2,5,7,8},{3,6,8,9}};
    float cm[4][4];
#pragma unroll
    for (int i = 0; i < 4; ++i)
#pragma unroll
        for (int j = 0; j < 4; ++j)
            cm[i][j] = dots[dmap[i][j]] * nn[i] * nn[j];

    // conv1 (4,1,2,2) VALID -> 4x3x3, relu
    float o1[4][3][3];
#pragma unroll
    for (int cc = 0; cc < 4; ++cc) {
        float w00 = c1w[cc*4+0], w01 = c1w[cc*4+1];
        float w10 = c1w[cc*4+2], w11 = c1w[cc*4+3];
        float bb = c1b[cc];
#pragma unroll
        for (int y = 0; y < 3; ++y)
#pragma unroll
            for (int x = 0; x < 3; ++x)
                o1[cc][y][x] = fmaxf(bb + w00*cm[y][x] + w01*cm[y][x+1]
                                        + w10*cm[y+1][x] + w11*cm[y+1][x+1], 0.f);
    }
    // conv2 (8,4,2,2) VALID -> 8x2x2, relu; flat dot scorer; sigmoid
    float score = scb[0];
#pragma unroll
    for (int oc = 0; oc < 8; ++oc) {
        float bb = c2b[oc];
#pragma unroll
        for (int y = 0; y < 2; ++y)
#pragma unroll
            for (int x = 0; x < 2; ++x) {
                float s = bb;
#pragma unroll
                for (int ic = 0; ic < 4; ++ic) {
                    const float* w = c2w + ((oc*4 + ic) * 4);
                    s += w[0]*o1[ic][y][x]   + w[1]*o1[ic][y][x+1]
                       + w[2]*o1[ic][y+1][x] + w[3]*o1[ic][y+1][x+1];
                }
                score += fmaxf(s, 0.f) * scw[oc*4 + y*2 + x];
            }
    }
    out[gw] = __fdividef(1.f, 1.f + __expf(-score));
}

extern "C" void kernel_launch(void* const* d_in, const int* in_sizes, int n_in,
                              void* d_out, int out_size) {
    const int*   word_ids = (const int*)  d_in[0];
    const int*   lengths  = (const int*)  d_in[1];
    const float* emb      = (const float*)d_in[2];
    const float* Wih      = (const float*)d_in[3];
    const float* Whh      = (const float*)d_in[4];
    const float* bih      = (const float*)d_in[5];
    const float* bhh      = (const float*)d_in[6];
    const float* c1w      = (const float*)d_in[7];
    const float* c1b      = (const float*)d_in[8];
    const float* c2w      = (const float*)d_in[9];
    const float* c2b      = (const float*)d_in[10];
    const float* scw      = (const float*)d_in[11];
    const float* scb      = (const float*)d_in[12];
    float* out = (float*)d_out;

    k_gates<<<VV, G4H>>>(emb, Wih, bih, bhh);
    k_zero<<<1, 32>>>();
    k_hist<<<BN_TOT/256, 256>>>(lengths);
    k_scan<<<1, 1>>>();
    k_scatter<<<BN_TOT/256, 256>>>(lengths);
    k_lstm<<<BN_TOT/32, 256>>>(word_ids, lengths, Whh);
    k_head<<<BB/8, 256>>>(c1w, c1b, c2w, c2b, scw, scb, out);
}

// round 4
// speedup vs baseline: 1.2779x; 1.2779x over previous
#include <cuda_runtime.h>

#define BB   8192
#define NW   4
#define LL   16
#define EE   128
#define HH   128
#define VV   64
#define BN_TOT (BB*NW)
#define G4H  512

typedef unsigned long long u64;

__device__ __align__(16) float g_G[VV * G4H];          // input gates per vocab word
__device__ __align__(16) float g_Wt[HH * G4H];         // W_hh transposed: [k][j]
__device__ __align__(16) float g_reps[(size_t)BN_TOT * HH];
__device__ int g_perm[BN_TOT];
__device__ int g_cursor[16];

__device__ __forceinline__ u64 dup2(float a) {
    u64 v; asm("mov.b64 %0, {%1, %1};" : "=l"(v) : "f"(a)); return v;
}
__device__ __forceinline__ u64 pk(float a, float b) {
    u64 v; asm("mov.b64 %0, {%1, %2};" : "=l"(v) : "f"(a), "f"(b)); return v;
}
__device__ __forceinline__ void unpk(u64 v, float& a, float& b) {
    asm("mov.b64 {%0, %1}, %2;" : "=f"(a), "=f"(b) : "l"(v));
}
__device__ __forceinline__ float tanha(float x) {
    float y; asm("tanh.approx.f32 %0, %1;" : "=f"(y) : "f"(x)); return y;
}
__device__ __forceinline__ float sigma_(float x) {        // sigmoid via tanh
    return fmaf(0.5f, tanha(0.5f * x), 0.5f);
}
__device__ __forceinline__ float sigm_exact(float x) {
    return __fdividef(1.f, 1.f + __expf(-x));
}

// ---- one-block: histogram lengths (desc bins) + exclusive scan -> g_cursor ----
__global__ void k_prep(const int* __restrict__ lengths) {
    __shared__ int bins[16][33];
    int tid = threadIdx.x, w = tid >> 5;
    for (int i = tid; i < 16 * 33; i += 1024) (&bins[0][0])[i] = 0;
    __syncthreads();
    for (int i = tid; i < BN_TOT; i += 1024)
        atomicAdd(&bins[16 - lengths[i]][w], 1);
    __syncthreads();
    if (tid < 16) {
        int s = 0;
        for (int ww = 0; ww < 32; ++ww) s += bins[tid][ww];
        bins[tid][32] = s;
    }
    __syncthreads();
    if (tid == 0) {
        int cum = 0;
        for (int b = 0; b < 16; ++b) { g_cursor[b] = cum; cum += bins[b][32]; }
    }
}

// ---- scatter rows into length-descending order ----
__global__ void k_scatter(const int* __restrict__ lengths) {
    __shared__ int cnt[16], base[16];
    int tid = threadIdx.x;
    if (tid < 16) cnt[tid] = 0;
    __syncthreads();
    int bn  = blockIdx.x * 256 + tid;
    int bin = 16 - lengths[bn];
    int rank = atomicAdd(&cnt[bin], 1);
    __syncthreads();
    if (tid < 16) base[tid] = atomicAdd(&g_cursor[tid], cnt[tid]);
    __syncthreads();
    g_perm[base[bin] + rank] = bn;
}

// ---- blocks 0..63: G[v][j] = emb[v].W_ih[j] + b_ih[j] + b_hh[j]
// ---- blocks 64..95: transpose W_hh -> g_Wt[k][j]
__global__ void k_gates(const float* __restrict__ emb, const float* __restrict__ Wih,
                        const float* __restrict__ bih, const float* __restrict__ bhh,
                        const float* __restrict__ Whh) {
    int j = threadIdx.x;
    if (blockIdx.x < 64) {
        int v = blockIdx.x;
        const float* e = emb + v * EE;
        const float* w = Wih + j * EE;
        float s = bih[j] + bhh[j];
#pragma unroll 8
        for (int k = 0; k < EE; ++k) s = fmaf(e[k], w[k], s);
        g_G[v * G4H + j] = s;
    } else {
        int kb = (blockIdx.x - 64) * 4;
#pragma unroll
        for (int kk = 0; kk < 4; ++kk)
            g_Wt[(kb + kk) * G4H + j] = Whh[j * HH + kb + kk];
    }
}

// ---- masked LSTM over length-sorted rows ----
// CTA = 32 rows, 256 threads. Warp (rh,ch): rh owns rows [8rh,8rh+8), ch a
// 64-wide hidden half; thread cols {g*128 + 64*ch + 2*lane, +1}. W fetched via
// coalesced LDG.64 from transposed g_Wt (L1-resident, warp-staggered k order).
// Only the 2 warps sharing a row group synchronize (named barrier), and each
// group runs to its own max length.
__global__ __launch_bounds__(256, 2)
void k_lstm(const int* __restrict__ word_ids, const int* __restrict__ lengths) {
    __shared__ __align__(16) float sH[32][128];
    __shared__ int sBn[32], sLen[32], sWid[32][LL];

    int tid  = threadIdx.x;
    int lane = tid & 31;
    int wrp  = tid >> 5;
    int rh   = wrp >> 1;
    int ch   = wrp & 1;
    int base = blockIdx.x * 32;
    int colh = 64 * ch + 2 * lane;
    int row0 = rh * 8;

    if (tid < 32) {
        int bn = g_perm[base + tid];
        sBn[tid] = bn; sLen[tid] = lengths[bn];
    }
    __syncthreads();
    for (int i = tid; i < 32 * LL; i += 256) {
        int r = i >> 4, t = i & 15;
        sWid[r][t] = word_ids[sBn[r] * LL + t];
    }
    for (int i = tid; i < 32 * 128; i += 256) (&sH[0][0])[i] = 0.f;
    __syncthreads();

    int tLen = 0;
#pragma unroll
    for (int r = 0; r < 8; ++r) tLen = max(tLen, sLen[row0 + r]);

    // warp-staggered k start: 16 warps/SM spread over 64 k-pair slots
    int sstart = ((wrp + ((blockIdx.x & 1) << 3)) & 15) << 2;

    float c[8][2];
#pragma unroll
    for (int r = 0; r < 8; ++r) { c[r][0] = 0.f; c[r][1] = 0.f; }

    for (int t = 0; t < tLen; ++t) {
        u64 acc[8][4];
#pragma unroll
        for (int r = 0; r < 8; ++r) {
            const u64* Gp = (const u64*)(g_G + sWid[row0 + r][t] * G4H + colh);
#pragma unroll
            for (int g = 0; g < 4; ++g) acc[r][g] = Gp[g * 64];
        }
        for (int kc = 0; kc < 64; ++kc) {
            int k = (((kc + sstart) & 63) << 1);
            float2 h2[8];
#pragma unroll
            for (int r = 0; r < 8; ++r)
                h2[r] = *(const float2*)&sH[row0 + r][k];
            u64 wA[4], wB[4];
            const float* wk = g_Wt + k * G4H + colh;
#pragma unroll
            for (int g = 0; g < 4; ++g) wA[g] = *(const u64*)(wk + g * 128);
#pragma unroll
            for (int g = 0; g < 4; ++g) wB[g] = *(const u64*)(wk + G4H + g * 128);
#pragma unroll
            for (int r = 0; r < 8; ++r) {
                u64 ha = dup2(h2[r].x);
#pragma unroll
                for (int g = 0; g < 4; ++g)
                    asm("fma.rn.f32x2 %0, %1, %2, %0;"
                        : "+l"(acc[r][g]) : "l"(ha), "l"(wA[g]));
            }
#pragma unroll
            for (int r = 0; r < 8; ++r) {
                u64 hb = dup2(h2[r].y);
#pragma unroll
                for (int g = 0; g < 4; ++g)
                    asm("fma.rn.f32x2 %0, %1, %2, %0;"
                        : "+l"(acc[r][g]) : "l"(hb), "l"(wB[g]));
            }
        }
        // pair barrier: h reads of this step complete (warps 2rh, 2rh+1)
        asm volatile("bar.sync %0, 64;" :: "r"(rh + 1) : "memory");
#pragma unroll
        for (int r = 0; r < 8; ++r) {
            int row = row0 + r;
            if (t < sLen[row]) {
                float i0, i1, f0, f1, gg0, gg1, o0, o1;
                unpk(acc[r][0], i0, i1); unpk(acc[r][1], f0, f1);
                unpk(acc[r][2], gg0, gg1); unpk(acc[r][3], o0, o1);
                float c0 = fmaf(sigma_(f0), c[r][0], sigma_(i0) * tanha(gg0));
                float c1 = fmaf(sigma_(f1), c[r][1], sigma_(i1) * tanha(gg1));
                c[r][0] = c0; c[r][1] = c1;
                *(u64*)(&sH[row][colh]) = pk(sigma_(o0) * tanha(c0),
                                             sigma_(o1) * tanha(c1));
            }
        }
        // pair barrier: h writes visible before next step's reads
        asm volatile("bar.sync %0, 64;" :: "r"(rh + 1) : "memory");
    }
#pragma unroll
    for (int r = 0; r < 8; ++r) {
        size_t bn = (size_t)sBn[row0 + r];
        *(u64*)(g_reps + bn * HH + colh) = pk(c[r][0], c[r][1]);
    }
}

// ---- head: cos 4x4 -> conv1 relu -> conv2 relu -> scorer -> sigmoid ----
__global__ void k_head(const float* __restrict__ c1w, const float* __restrict__ c1b,
                       const float* __restrict__ c2w, const float* __restrict__ c2b,
                       const float* __restrict__ scw, const float* __restrict__ scb,
                       float* __restrict__ out) {
    int gw   = blockIdx.x * 8 + (threadIdx.x >> 5);   // one warp per batch b
    int lane = threadIdx.x & 31;
    if (gw >= BB) return;

    const float* rp = g_reps + (size_t)gw * (NW * HH);
    float4 rv[4];
#pragma unroll
    for (int i = 0; i < 4; ++i)
        rv[i] = *(const float4*)(rp + i * HH + lane * 4);

    const int pi[10] = {0,0,0,0,1,1,1,2,2,3};
    const int pj[10] = {0,1,2,3,1,2,3,2,3,3};
    float dots[10];
#pragma unroll
    for (int d = 0; d < 10; ++d) {
        float4 a = rv[pi[d]], b = rv[pj[d]];
        float s = a.x*b.x + a.y*b.y + a.z*b.z + a.w*b.w;
#pragma unroll
        for (int o = 16; o; o >>= 1) s += __shfl_xor_sync(0xffffffffu, s, o);
        dots[d] = s;
    }
    if (lane) return;

    float nn[4] = { rsqrtf(dots[0]), rsqrtf(dots[4]), rsqrtf(dots[7]), rsqrtf(dots[9]) };
    const int dmap[4][4] = {{0,1,2,3},{1,4,5,6},{2,5,7,8},{3,6,8,9}};
    float cm[4][4];
#pragma unroll
    for (int i = 0; i < 4; ++i)
#pragma unroll
        for (int j = 0; j < 4; ++j)
            cm[i][j] = dots[dmap[i][j]] * nn[i] * nn[j];

    float o1[4][3][3];
#pragma unroll
    for (int cc = 0; cc < 4; ++cc) {
        float w00 = c1w[cc*4+0], w01 = c1w[cc*4+1];
        float w10 = c1w[cc*4+2], w11 = c1w[cc*4+3];
        float bb = c1b[cc];
#pragma unroll
        for (int y = 0; y < 3; ++y)
#pragma unroll
            for (int x = 0; x < 3; ++x)
                o1[cc][y][x] = fmaxf(bb + w00*cm[y][x] + w01*cm[y][x+1]
                                        + w10*cm[y+1][x] + w11*cm[y+1][x+1], 0.f);
    }
    float score = scb[0];
#pragma unroll
    for (int oc = 0; oc < 8; ++oc) {
        float bb = c2b[oc];
#pragma unroll
        for (int y = 0; y < 2; ++y)
#pragma unroll
            for (int x = 0; x < 2; ++x) {
                float s = bb;
#pragma unroll
                for (int ic = 0; ic < 4; ++ic) {
                    const float* w = c2w + ((oc*4 + ic) * 4);
                    s += w[0]*o1[ic][y][x]   + w[1]*o1[ic][y][x+1]
                       + w[2]*o1[ic][y+1][x] + w[3]*o1[ic][y+1][x+1];
                }
                score += fmaxf(s, 0.f) * scw[oc*4 + y*2 + x];
            }
    }
    out[gw] = sigm_exact(score);
}

extern "C" void kernel_launch(void* const* d_in, const int* in_sizes, int n_in,
                              void* d_out, int out_size) {
    const int*   word_ids = (const int*)  d_in[0];
    const int*   lengths  = (const int*)  d_in[1];
    const float* emb      = (const float*)d_in[2];
    const float* Wih      = (const float*)d_in[3];
    const float* Whh      = (const float*)d_in[4];
    const float* bih      = (const float*)d_in[5];
    const float* bhh      = (const float*)d_in[6];
    const float* c1w      = (const float*)d_in[7];
    const float* c1b      = (const float*)d_in[8];
    const float* c2w      = (const float*)d_in[9];
    const float* c2b      = (const float*)d_in[10];
    const float* scw      = (const float*)d_in[11];
    const float* scb      = (const float*)d_in[12];
    float* out = (float*)d_out;

    k_prep<<<1, 1024>>>(lengths);
    k_scatter<<<BN_TOT/256, 256>>>(lengths);
    k_gates<<<96, G4H>>>(emb, Wih, bih, bhh, Whh);
    k_lstm<<<BN_TOT/32, 256>>>(word_ids, lengths);
    k_head<<<BB/8, 256>>>(c1w, c1b, c2w, c2b, scw, scb, out);
}